// round 13
// baseline (speedup 1.0000x reference)
#include <cuda_runtime.h>
#include <cstdint>
#include <math.h>

#define D_DEPTH 128
#define BEV 128
#define CELL (BEV*BEV)
#define LOG_U3 (-1.0986f)
#define EPSC 1e-7f

#define ST_PITCH4 25      /* float4 pitch per pixel: 24 payload + 1 pad; 400B = 4 mod 128B banks */

// Interleaved class table: per BEV cell a float4 {logc0, logc1, logc2, 0}.
__device__ float4 g_logcp4[4 * CELL];

// ---------------------------------------------------------------------------
// Kernel 1: bev_logits (B,2,128,128) -> interleaved log class probs
// ---------------------------------------------------------------------------
__global__ void bev_table_kernel(const float* __restrict__ bev, int B) {
    int idx = blockIdx.x * blockDim.x + threadIdx.x;
    if (idx >= B * CELL) return;
    int b = idx / CELL, zx = idx - b * CELL;
    float l0 = bev[(b * 2 + 0) * CELL + zx];
    float l1 = bev[(b * 2 + 1) * CELL + zx];
    float p0 = 1.0f / (1.0f + __expf(-l0));
    float p1 = 1.0f / (1.0f + __expf(-l1));
    p0 = fminf(fmaxf(p0, EPSC), 1.0f - EPSC);
    p1 = fminf(fmaxf(p1, EPSC), 1.0f - EPSC);
    g_logcp4[b * CELL + zx] = make_float4(
        __logf(1.0f - p1), __logf(p1 * p0), __logf(p1 * (1.0f - p0)), 0.0f);
}

__device__ __forceinline__ unsigned int smem_u32(const void* p) {
    return (unsigned int)__cvta_generic_to_shared(p);
}

// ---------------------------------------------------------------------------
// Kernel 2: block = 32 pixels x 128 depths, 256 threads (32 lanes x 8 warps).
// Thread (tx,ty): pixel tx, depths {32c + 4ty + kk} in 16 registers.
// Phase 3: lane=pixel gather (warp-uniform vz) -> smem stage; the smem->gmem
// leg is offloaded to the bulk-copy engine (32 x 384B per chunk), TRIPLE
// buffered so the only read-drain wait (c=3 on buffer 0) is long since done.
// PDL gates the first table read against bev_table_kernel.
// ---------------------------------------------------------------------------
__global__ __launch_bounds__(256, 5) void decode_kernel(
    const float* __restrict__ dl,    // (B, D, H, W)
    const float* __restrict__ invK,  // (B, 4, 4)
    float* __restrict__ out,         // (B, H, W, D, 3)
    int H, int W)
{
    __shared__ float red_max[8][32];
    __shared__ float red_sum[8][32];
    __shared__ float cam0s[32], cam1s[32], cam2s[32];
    __shared__ float4 stageF4[3][32 * ST_PITCH4];   // triple buffer, 3 x 12.5 KB

    const int tid = threadIdx.x;
    const int tx = tid & 31;
    const int ty = tid >> 5;
    const int tilesPerRow = W >> 5;

    int bid = blockIdx.x;
    int w0 = (bid % tilesPerRow) << 5;
    int h  = (bid / tilesPerRow) % H;
    int b  =  bid / (tilesPerRow * H);

    const size_t HW = (size_t)H * W;
    const float* bp = dl + ((size_t)b * D_DEPTH + (size_t)(ty << 2)) * HW
                        + (size_t)h * W + w0 + tx;

    // Phase 1: 16 coalesced LDGs straight into registers.
    float lg[16];
    #pragma unroll
    for (int c = 0; c < 4; c++)
        #pragma unroll
        for (int kk = 0; kk < 4; kk++)
            lg[c * 4 + kk] = __ldg(&bp[(size_t)((c << 5) + kk) * HW]);

    if (ty == 0) {
        const float* k = invK + (size_t)b * 16;
        float x = (float)(w0 + tx), y = (float)h;
        cam0s[tx] = k[0] * x + k[1] * y + k[2];
        cam1s[tx] = k[4] * x + k[5] * y + k[6];
        cam2s[tx] = k[8] * x + k[9] * y + k[10];
    }

    // Phase 2a: per-pixel max over D (redundant combine: 1 barrier)
    float m = lg[0];
    #pragma unroll
    for (int j = 1; j < 16; j++) m = fmaxf(m, lg[j]);
    red_max[ty][tx] = m;
    __syncthreads();

    float mpx = red_max[0][tx];
    #pragma unroll
    for (int r = 1; r < 8; r++) mpx = fmaxf(mpx, red_max[r][tx]);

    // Phase 2b: per-pixel sum(exp(x-max)) (redundant combine: 1 barrier)
    float s = 0.0f;
    #pragma unroll
    for (int j = 0; j < 16; j++) s += __expf(lg[j] - mpx);
    red_sum[ty][tx] = s;
    __syncthreads();

    float ss = red_sum[0][tx];
    #pragma unroll
    for (int r = 1; r < 8; r++) ss += red_sum[r][tx];
    const float sh = -mpx - __logf(ss);          // log_softmax shift

    const float ca0 = cam0s[tx], ca1 = cam1s[tx], ca2 = cam2s[tx];

    // PDL gate: bev_table_kernel must be complete before the first table read.
    cudaGridDependencySynchronize();

    float* outp = out + (((size_t)b * H + h) * W + w0) * (size_t)(D_DEPTH * 3);
    const float4* t4 = &g_logcp4[(size_t)b * CELL];

    // Phase 3: 4 chunks of 32 depths; stage in smem, bulk-engine stores.
    #pragma unroll
    for (int c = 0; c < 4; c++) {
        float4* stg = stageF4[c % 3];
        const float ub = 4.5f + (float)((c << 5) + (ty << 2));  // u = d+4.5 exact

        float vals[12];
        #pragma unroll
        for (int kk = 0; kk < 4; kk++) {
            float u   = ub + (float)kk;
            float dlp = lg[c * 4 + kk] + sh;
            float vxf = fmaf(u,  ca0,  64.0f);   // (X - X_MIN)/RES
            float vzf = fmaf(-u, ca2, 132.0f);   // (Z + Z_MAX)/RES
            float qy  = -u * ca1;                // Y/RES ; trunc<=0 <=> qy<1
            int vx = (int)vxf;
            int vz = (int)vzf;
            bool valid = ((unsigned)vx < (unsigned)BEV) &
                         ((unsigned)vz < (unsigned)BEV) & (qy < 1.0f);
            float4 t = make_float4(LOG_U3, LOG_U3, LOG_U3, 0.0f);
            if (valid) t = __ldg(&t4[vz * BEV + vx]);   // warp-uniform vz
            vals[kk * 3 + 0] = t.x + dlp;
            vals[kk * 3 + 1] = t.y + dlp;
            vals[kk * 3 + 2] = t.z + dlp;
        }

        // Buffer-reuse guard (only c=3 reuses buffer 0): the group issued at
        // c-3 must have drained its smem reads. It was issued ~3 chunk-times
        // ago, so this wait is expected to be a no-op.
        if (c == 3) {
            if (tid < 32)
                asm volatile("cp.async.bulk.wait_group.read 2;" ::: "memory");
            __syncthreads();
        }

        #pragma unroll
        for (int w = 0; w < 3; w++) {
            stg[ST_PITCH4 * tx + 3 * ty + w] =
                make_float4(vals[4 * w + 0], vals[4 * w + 1],
                            vals[4 * w + 2], vals[4 * w + 3]);
        }
        __syncthreads();

        // 32 x 384B bulk copies smem -> gmem (lane = pixel), one group/chunk.
        if (tid < 32) {
            asm volatile("fence.proxy.async.shared::cta;" ::: "memory");
            unsigned int src = smem_u32(&stg[ST_PITCH4 * tid]);
            const float* dst = outp + ((size_t)tid * 96 + c * 24) * 4;
            asm volatile(
                "cp.async.bulk.global.shared::cta.bulk_group [%0], [%1], %2;"
                :: "l"(dst), "r"(src), "r"(384u) : "memory");
            asm volatile("cp.async.bulk.commit_group;" ::: "memory");
        }
    }

    // Write-visibility drain before exit.
    if (tid < 32)
        asm volatile("cp.async.bulk.wait_group 0;" ::: "memory");
}

// ---------------------------------------------------------------------------
extern "C" void kernel_launch(void* const* d_in, const int* in_sizes, int n_in,
                              void* d_out, int out_size) {
    const float* depth = (const float*)d_in[0];   // depth_logits (B,128,H,W)
    const float* bev   = (const float*)d_in[1];   // bev_logits   (B,2,128,128)
    const float* invK  = (const float*)d_in[2];   // inv_K        (B,4,4)
    float* out = (float*)d_out;

    int B = in_sizes[2] / 16;
    long long HW = (long long)in_sizes[0] / ((long long)B * D_DEPTH);
    int W = 1;
    while ((long long)W * W < HW) W <<= 1;        // square, power-of-two dims
    int H = (int)(HW / W);

    bev_table_kernel<<<(B * CELL + 255) / 256, 256>>>(bev, B);

    // decode with programmatic dependent launch: may start while bev_table
    // runs; cudaGridDependencySynchronize() inside gates the table reads.
    cudaLaunchConfig_t cfg = {};
    cfg.gridDim  = dim3((unsigned)(B * H * (W / 32)));
    cfg.blockDim = dim3(256);
    cfg.dynamicSmemBytes = 0;
    cfg.stream = 0;                    // legacy default stream (same as <<<>>>)
    cudaLaunchAttribute attrs[1];
    attrs[0].id = cudaLaunchAttributeProgrammaticStreamSerialization;
    attrs[0].val.programmaticStreamSerializationAllowed = 1;
    cfg.attrs = attrs;
    cfg.numAttrs = 1;
    cudaLaunchKernelEx(&cfg, decode_kernel, depth, invK, out, H, W);
}

// round 14
// speedup vs baseline: 1.1189x; 1.1189x over previous
#include <cuda_runtime.h>
#include <cstdint>
#include <math.h>

#define D_DEPTH 128
#define BEV 128
#define CELL (BEV*BEV)
#define LOG_U3 (-1.0986f)
#define EPSC 1e-7f

#define ST_PITCH4 25      /* float4 pitch: 100 words = 4 mod 32 banks -> conflict-free */

// Interleaved class table: per BEV cell a float4 {logc0, logc1, logc2, 0}.
__device__ float4 g_logcp4[4 * CELL];

// ---------------------------------------------------------------------------
// Kernel 1: bev_logits (B,2,128,128) -> interleaved log class probs.
// Each thread triggers PDL dependent launch right after its stores.
// ---------------------------------------------------------------------------
__global__ void bev_table_kernel(const float* __restrict__ bev, int B) {
    int idx = blockIdx.x * blockDim.x + threadIdx.x;
    if (idx < B * CELL) {
        int b = idx / CELL, zx = idx - b * CELL;
        float l0 = bev[(b * 2 + 0) * CELL + zx];
        float l1 = bev[(b * 2 + 1) * CELL + zx];
        float p0 = 1.0f / (1.0f + __expf(-l0));
        float p1 = 1.0f / (1.0f + __expf(-l1));
        p0 = fminf(fmaxf(p0, EPSC), 1.0f - EPSC);
        p1 = fminf(fmaxf(p1, EPSC), 1.0f - EPSC);
        g_logcp4[b * CELL + zx] = make_float4(
            __logf(1.0f - p1), __logf(p1 * p0), __logf(p1 * (1.0f - p0)), 0.0f);
    }
    // Early PDL trigger: this CTA's table writes are done.
    asm volatile("griddepcontrol.launch_dependents;" ::: "memory");
}

// ---------------------------------------------------------------------------
// Kernel 2: block = 32 pixels x 128 depths, 256 threads (32 lanes x 8 warps).
// Thread (tx,ty): pixel tx, depths {32c + 4ty + kk} in 16 registers.
// Launched with PDL: phases 1-2 overlap the bev_table kernel; a grid
// dependency sync gates phase 3 (first g_logcp4 read).
// (256,7): reg cap 36 -- balances spill traffic vs occupancy.
// ---------------------------------------------------------------------------
__global__ __launch_bounds__(256, 7) void decode_kernel(
    const float* __restrict__ dl,    // (B, D, H, W)
    const float* __restrict__ invK,  // (B, 4, 4)
    float* __restrict__ out,         // (B, H, W, D, 3)
    int H, int W)
{
    __shared__ float red_max[8][32];
    __shared__ float red_sum[8][32];
    __shared__ float cam0s[32], cam1s[32], cam2s[32];
    __shared__ float4 stageF4[2][32 * ST_PITCH4];   // double buffer, 2 x 12.8 KB

    const int tid = threadIdx.x;
    const int tx = tid & 31;
    const int ty = tid >> 5;
    const int tilesPerRow = W >> 5;

    int bid = blockIdx.x;
    int w0 = (bid % tilesPerRow) << 5;
    int h  = (bid / tilesPerRow) % H;
    int b  =  bid / (tilesPerRow * H);

    const size_t HW = (size_t)H * W;
    const float* bp = dl + ((size_t)b * D_DEPTH + (size_t)(ty << 2)) * HW
                        + (size_t)h * W + w0 + tx;

    // Phase 1: 16 coalesced LDGs straight into registers.
    float lg[16];
    #pragma unroll
    for (int c = 0; c < 4; c++)
        #pragma unroll
        for (int kk = 0; kk < 4; kk++)
            lg[c * 4 + kk] = __ldg(&bp[(size_t)((c << 5) + kk) * HW]);

    if (ty == 0) {
        const float* k = invK + (size_t)b * 16;
        float x = (float)(w0 + tx), y = (float)h;
        cam0s[tx] = k[0] * x + k[1] * y + k[2];
        cam1s[tx] = k[4] * x + k[5] * y + k[6];
        cam2s[tx] = k[8] * x + k[9] * y + k[10];
    }

    // Phase 2a: per-pixel max over D (redundant combine: 1 barrier)
    float m = lg[0];
    #pragma unroll
    for (int j = 1; j < 16; j++) m = fmaxf(m, lg[j]);
    red_max[ty][tx] = m;
    __syncthreads();

    float mpx = red_max[0][tx];
    #pragma unroll
    for (int r = 1; r < 8; r++) mpx = fmaxf(mpx, red_max[r][tx]);

    // Phase 2b: per-pixel sum(exp(x-max)) (redundant combine: 1 barrier)
    float s = 0.0f;
    #pragma unroll
    for (int j = 0; j < 16; j++) s += __expf(lg[j] - mpx);
    red_sum[ty][tx] = s;
    __syncthreads();

    float ss = red_sum[0][tx];
    #pragma unroll
    for (int r = 1; r < 8; r++) ss += red_sum[r][tx];
    const float sh = -mpx - __logf(ss);          // log_softmax shift

    const float ca0 = cam0s[tx], ca1 = cam1s[tx], ca2 = cam2s[tx];

    // PDL gate: bev_table writes must be visible before the first table read.
    cudaGridDependencySynchronize();

    float* outp = out + (((size_t)b * H + h) * W + w0) * (size_t)(D_DEPTH * 3);
    float4* og4 = (float4*)outp;
    const float4* t4 = &g_logcp4[(size_t)b * CELL];

    const int px_o = tid >> 3;          // 3b pixel (shift-only mapping)
    const int tq   = tid & 7;

    // Phase 3: 4 chunks of 32 depths, double-buffered staging (1 sync/chunk)
    #pragma unroll
    for (int c = 0; c < 4; c++) {
        float4* stg = stageF4[c & 1];
        const float ub = 4.5f + (float)((c << 5) + (ty << 2));  // u = d+4.5 exact

        float vals[12];
        #pragma unroll
        for (int kk = 0; kk < 4; kk++) {
            float u   = ub + (float)kk;
            float dlp = lg[c * 4 + kk] + sh;
            float vxf = fmaf(u,  ca0,  64.0f);   // (X - X_MIN)/RES
            float vzf = fmaf(-u, ca2, 132.0f);   // (Z + Z_MAX)/RES
            float qy  = -u * ca1;                // Y/RES ; trunc<=0 <=> qy<1
            int vx = (int)vxf;
            int vz = (int)vzf;
            bool valid = ((unsigned)vx < (unsigned)BEV) &
                         ((unsigned)vz < (unsigned)BEV) & (qy < 1.0f);
            float4 t = make_float4(LOG_U3, LOG_U3, LOG_U3, 0.0f);
            if (valid) t = __ldg(&t4[vz * BEV + vx]);   // warp-uniform vz
            vals[kk * 3 + 0] = t.x + dlp;
            vals[kk * 3 + 1] = t.y + dlp;
            vals[kk * 3 + 2] = t.z + dlp;
        }
        #pragma unroll
        for (int w = 0; w < 3; w++) {
            stg[ST_PITCH4 * tx + 3 * ty + w] =
                make_float4(vals[4 * w + 0], vals[4 * w + 1],
                            vals[4 * w + 2], vals[4 * w + 3]);
        }
        __syncthreads();

        // Phase 3b: wavefront-exact copy stage -> gmem (shift-only indexing)
        #pragma unroll
        for (int r = 0; r < 3; r++) {
            int j4 = tq + (r << 3);          // 0..23
            float4 v = stg[ST_PITCH4 * px_o + j4];
            __stcs(&og4[(size_t)px_o * 96 + c * 24 + j4], v);
        }
        // no second sync: sync(c+1) after STS(c+1) to the OTHER buffer
        // guarantees 3b(c) completed before buffer (c&1) is rewritten at c+2
    }
}

// ---------------------------------------------------------------------------
extern "C" void kernel_launch(void* const* d_in, const int* in_sizes, int n_in,
                              void* d_out, int out_size) {
    const float* depth = (const float*)d_in[0];   // depth_logits (B,128,H,W)
    const float* bev   = (const float*)d_in[1];   // bev_logits   (B,2,128,128)
    const float* invK  = (const float*)d_in[2];   // inv_K        (B,4,4)
    float* out = (float*)d_out;

    int B = in_sizes[2] / 16;
    long long HW = (long long)in_sizes[0] / ((long long)B * D_DEPTH);
    int W = 1;
    while ((long long)W * W < HW) W <<= 1;        // square, power-of-two dims
    int H = (int)(HW / W);

    bev_table_kernel<<<(B * CELL + 255) / 256, 256>>>(bev, B);

    // decode with programmatic dependent launch: may start while bev_table
    // runs; cudaGridDependencySynchronize() inside gates the table reads.
    cudaLaunchConfig_t cfg = {};
    cfg.gridDim  = dim3((unsigned)(B * H * (W / 32)));
    cfg.blockDim = dim3(256);
    cfg.dynamicSmemBytes = 0;
    cfg.stream = 0;                    // legacy default stream (same as <<<>>>)
    cudaLaunchAttribute attrs[1];
    attrs[0].id = cudaLaunchAttributeProgrammaticStreamSerialization;
    attrs[0].val.programmaticStreamSerializationAllowed = 1;
    cfg.attrs = attrs;
    cfg.numAttrs = 1;
    cudaLaunchKernelEx(&cfg, decode_kernel, depth, invK, out, H, W);
}

// round 15
// speedup vs baseline: 1.1461x; 1.0243x over previous
#include <cuda_runtime.h>
#include <cstdint>
#include <math.h>

#define D_DEPTH 128
#define BEV 128
#define CELL (BEV*BEV)
#define LOG_U3 (-1.0986f)
#define EPSC 1e-7f

#define ST_PITCH4 25      /* float4 pitch: 100 words = 4 mod 32 banks */

// Interleaved class table: per BEV cell a float4 {logc0, logc1, logc2, 0}.
__device__ float4 g_logcp4[4 * CELL];

// ---------------------------------------------------------------------------
// Kernel 1: bev_logits (B,2,128,128) -> interleaved log class probs
// ---------------------------------------------------------------------------
__global__ void bev_table_kernel(const float* __restrict__ bev, int B) {
    int idx = blockIdx.x * blockDim.x + threadIdx.x;
    if (idx >= B * CELL) return;
    int b = idx / CELL, zx = idx - b * CELL;
    float l0 = bev[(b * 2 + 0) * CELL + zx];
    float l1 = bev[(b * 2 + 1) * CELL + zx];
    float p0 = 1.0f / (1.0f + __expf(-l0));
    float p1 = 1.0f / (1.0f + __expf(-l1));
    p0 = fminf(fmaxf(p0, EPSC), 1.0f - EPSC);
    p1 = fminf(fmaxf(p1, EPSC), 1.0f - EPSC);
    g_logcp4[b * CELL + zx] = make_float4(
        __logf(1.0f - p1), __logf(p1 * p0), __logf(p1 * (1.0f - p0)), 0.0f);
}

// ---------------------------------------------------------------------------
// Kernel 2: block = 32 pixels x 128 depths, 256 threads (32 lanes x 8 warps).
// Thread (tx,ty): pixel tx, depths {32c + 4ty + kk} in 16 registers.
// Phase 3 gathers are software-pipelined ONE CHUNK AHEAD: loads for chunk
// c+1 are issued before the chunk-c barrier, so their ~L2 latency is hidden
// under the sync + 3b copy instead of being exposed per chunk.
// ---------------------------------------------------------------------------
__global__ __launch_bounds__(256, 8) void decode_kernel(
    const float* __restrict__ dl,    // (B, D, H, W)
    const float* __restrict__ invK,  // (B, 4, 4)
    float* __restrict__ out,         // (B, H, W, D, 3)
    int H, int W)
{
    __shared__ float red_max[8][32];
    __shared__ float red_sum[8][32];
    __shared__ float cam0s[32], cam1s[32], cam2s[32];
    __shared__ float4 stageF4[2][32 * ST_PITCH4];   // double buffer, 2 x 12.8 KB

    const int tid = threadIdx.x;
    const int tx = tid & 31;
    const int ty = tid >> 5;
    const int tilesPerRow = W >> 5;

    int bid = blockIdx.x;
    int w0 = (bid % tilesPerRow) << 5;
    int h  = (bid / tilesPerRow) % H;
    int b  =  bid / (tilesPerRow * H);

    const size_t HW = (size_t)H * W;
    const float* bp = dl + ((size_t)b * D_DEPTH + (size_t)(ty << 2)) * HW
                        + (size_t)h * W + w0 + tx;

    // Phase 1: 16 coalesced LDGs straight into registers.
    float lg[16];
    #pragma unroll
    for (int c = 0; c < 4; c++)
        #pragma unroll
        for (int kk = 0; kk < 4; kk++)
            lg[c * 4 + kk] = __ldg(&bp[(size_t)((c << 5) + kk) * HW]);

    if (ty == 0) {
        const float* k = invK + (size_t)b * 16;
        float x = (float)(w0 + tx), y = (float)h;
        cam0s[tx] = k[0] * x + k[1] * y + k[2];
        cam1s[tx] = k[4] * x + k[5] * y + k[6];
        cam2s[tx] = k[8] * x + k[9] * y + k[10];
    }

    // Phase 2a: per-pixel max over D (redundant combine: 1 barrier)
    float m = lg[0];
    #pragma unroll
    for (int j = 1; j < 16; j++) m = fmaxf(m, lg[j]);
    red_max[ty][tx] = m;
    __syncthreads();

    float mpx = red_max[0][tx];
    #pragma unroll
    for (int r = 1; r < 8; r++) mpx = fmaxf(mpx, red_max[r][tx]);

    // Phase 2b: per-pixel sum(exp(x-max)) (redundant combine: 1 barrier)
    float s = 0.0f;
    #pragma unroll
    for (int j = 0; j < 16; j++) s += __expf(lg[j] - mpx);
    red_sum[ty][tx] = s;
    __syncthreads();

    float ss = red_sum[0][tx];
    #pragma unroll
    for (int r = 1; r < 8; r++) ss += red_sum[r][tx];
    const float sh = -mpx - __logf(ss);          // log_softmax shift

    // Fold shift into lg: lg now holds per-(pixel,depth) log-softmax values.
    #pragma unroll
    for (int j = 0; j < 16; j++) lg[j] += sh;

    const float ca0 = cam0s[tx], ca1 = cam1s[tx], ca2 = cam2s[tx];

    // PDL gate: bev_table writes must be visible before the first table read.
    cudaGridDependencySynchronize();

    float* outp = out + (((size_t)b * H + h) * W + w0) * (size_t)(D_DEPTH * 3);
    float4* og4 = (float4*)outp;
    const float4* t4 = &g_logcp4[(size_t)b * CELL];

    const int px_o = tid >> 3;          // 3b pixel (shift-only mapping)
    const int tq   = tid & 7;

    // Gather pipeline registers (one chunk in flight).
    float4 tg[4];

    // Prologue: issue chunk 0's gathers.
    {
        const float ub = 4.5f + (float)(ty << 2);
        #pragma unroll
        for (int kk = 0; kk < 4; kk++) {
            float u   = ub + (float)kk;
            float vxf = fmaf(u,  ca0,  64.0f);
            float vzf = fmaf(-u, ca2, 132.0f);
            float qy  = -u * ca1;
            int vx = (int)vxf;
            int vz = (int)vzf;
            bool valid = ((unsigned)vx < (unsigned)BEV) &
                         ((unsigned)vz < (unsigned)BEV) & (qy < 1.0f);
            tg[kk] = make_float4(LOG_U3, LOG_U3, LOG_U3, 0.0f);
            if (valid) tg[kk] = __ldg(&t4[vz * BEV + vx]);
        }
    }

    // Phase 3: 4 chunks of 32 depths, double-buffered staging (1 sync/chunk)
    #pragma unroll
    for (int c = 0; c < 4; c++) {
        float4* stg = stageF4[c & 1];

        // Consume in-flight gathers (issued one iteration ago).
        float vals[12];
        #pragma unroll
        for (int kk = 0; kk < 4; kk++) {
            float dlp = lg[c * 4 + kk];
            vals[kk * 3 + 0] = tg[kk].x + dlp;
            vals[kk * 3 + 1] = tg[kk].y + dlp;
            vals[kk * 3 + 2] = tg[kk].z + dlp;
        }

        // Issue NEXT chunk's gathers now: they fly during STS + sync + copy.
        if (c < 3) {
            const float ub = 4.5f + (float)(((c + 1) << 5) + (ty << 2));
            #pragma unroll
            for (int kk = 0; kk < 4; kk++) {
                float u   = ub + (float)kk;
                float vxf = fmaf(u,  ca0,  64.0f);
                float vzf = fmaf(-u, ca2, 132.0f);
                float qy  = -u * ca1;
                int vx = (int)vxf;
                int vz = (int)vzf;
                bool valid = ((unsigned)vx < (unsigned)BEV) &
                             ((unsigned)vz < (unsigned)BEV) & (qy < 1.0f);
                tg[kk] = make_float4(LOG_U3, LOG_U3, LOG_U3, 0.0f);
                if (valid) tg[kk] = __ldg(&t4[vz * BEV + vx]);
            }
        }

        #pragma unroll
        for (int w = 0; w < 3; w++) {
            stg[ST_PITCH4 * tx + 3 * ty + w] =
                make_float4(vals[4 * w + 0], vals[4 * w + 1],
                            vals[4 * w + 2], vals[4 * w + 3]);
        }
        __syncthreads();

        // Phase 3b: wavefront-exact copy stage -> gmem (shift-only indexing)
        #pragma unroll
        for (int r = 0; r < 3; r++) {
            int j4 = tq + (r << 3);          // 0..23
            float4 v = stg[ST_PITCH4 * px_o + j4];
            __stcs(&og4[(size_t)px_o * 96 + c * 24 + j4], v);
        }
        // no second sync: sync(c+1) after STS(c+1) to the OTHER buffer
        // guarantees 3b(c) completed before buffer (c&1) is rewritten at c+2
    }
}

// ---------------------------------------------------------------------------
extern "C" void kernel_launch(void* const* d_in, const int* in_sizes, int n_in,
                              void* d_out, int out_size) {
    const float* depth = (const float*)d_in[0];   // depth_logits (B,128,H,W)
    const float* bev   = (const float*)d_in[1];   // bev_logits   (B,2,128,128)
    const float* invK  = (const float*)d_in[2];   // inv_K        (B,4,4)
    float* out = (float*)d_out;

    int B = in_sizes[2] / 16;
    long long HW = (long long)in_sizes[0] / ((long long)B * D_DEPTH);
    int W = 1;
    while ((long long)W * W < HW) W <<= 1;        // square, power-of-two dims
    int H = (int)(HW / W);

    bev_table_kernel<<<(B * CELL + 255) / 256, 256>>>(bev, B);

    // decode with programmatic dependent launch: may start while bev_table
    // runs; cudaGridDependencySynchronize() inside gates the table reads.
    cudaLaunchConfig_t cfg = {};
    cfg.gridDim  = dim3((unsigned)(B * H * (W / 32)));
    cfg.blockDim = dim3(256);
    cfg.dynamicSmemBytes = 0;
    cfg.stream = 0;                    // legacy default stream (same as <<<>>>)
    cudaLaunchAttribute attrs[1];
    attrs[0].id = cudaLaunchAttributeProgrammaticStreamSerialization;
    attrs[0].val.programmaticStreamSerializationAllowed = 1;
    cfg.attrs = attrs;
    cfg.numAttrs = 1;
    cudaLaunchKernelEx(&cfg, decode_kernel, depth, invK, out, H, W);
}